// round 8
// baseline (speedup 1.0000x reference)
#include <cuda_runtime.h>
#include <cuda_bf16.h>
#include <math.h>

#define T_OBS 8
#define EPSBN 1e-5f

typedef unsigned int u32;
typedef unsigned long long u64;

#define MAXB 131072
#define WSTR 88   // padded k-stride (bf16): 176B rows, conflict-free ldmatrix

// ---------------- static device scratch ------------------------------------
__device__ float  g_h[MAXB * 64];
__device__ float  g_c[MAXB * 64];
__device__ float  g_z[MAXB * 16];
__device__ float  g_last[MAXB * 2];
__device__ __align__(16) __nv_bfloat16 g_Wh[256 * WSTR];
__device__ __align__(16) __nv_bfloat16 g_Wl[256 * WSTR];
__device__ float  g_bias[256];
__device__ double g_enc_stats[5];
__device__ double g_se2[2][5];
__device__ double g_hp2[2][32];
__device__ u32    g_barc = 0;
__device__ u32    g_barg = 0;

// ---------------- helpers ----------------------------------------------------
__device__ __forceinline__ float scalar_f(const void* p) {
    int iv = *(const int*)p;
    float fv = __int_as_float(iv);
    if (fv >= 1e-3f && fv <= 1e7f) return fv;
    return (float)iv;
}
__device__ __forceinline__ float fast_sig(float x) {
    float t; asm("ex2.approx.f32 %0, %1;" : "=f"(t) : "f"(-1.4426950408889634f * x));
    float r; asm("rcp.approx.f32 %0, %1;" : "=f"(r) : "f"(1.0f + t));
    return r;
}
__device__ __forceinline__ float fast_tanh(float x) {
    float t; asm("ex2.approx.f32 %0, %1;" : "=f"(t) : "f"(2.8853900817779268f * x));
    float r; asm("rcp.approx.f32 %0, %1;" : "=f"(r) : "f"(1.0f + t));
    return 1.0f - 2.0f * r;
}
__device__ __forceinline__ float wred(float v) {
#pragma unroll
    for (int o = 16; o > 0; o >>= 1) v += __shfl_down_sync(0xffffffffu, v, o);
    return v;
}
__device__ __forceinline__ u32 smem_u32(const void* p) {
    u32 a;
    asm("{ .reg .u64 t; cvta.to.shared.u64 t, %1; cvt.u32.u64 %0, t; }" : "=r"(a) : "l"(p));
    return a;
}
__device__ __forceinline__ void ldsm4(u32* r, u32 addr) {
    asm volatile("ldmatrix.sync.aligned.m8n8.x4.shared.b16 {%0,%1,%2,%3}, [%4];"
        : "=r"(r[0]), "=r"(r[1]), "=r"(r[2]), "=r"(r[3]) : "r"(addr));
}
__device__ __forceinline__ void mma16816(float* d, const u32* a, const u32* b) {
    asm volatile(
        "mma.sync.aligned.m16n8k16.row.col.f32.bf16.bf16.f32 "
        "{%0,%1,%2,%3},{%4,%5,%6,%7},{%8,%9},{%0,%1,%2,%3};"
        : "+f"(d[0]), "+f"(d[1]), "+f"(d[2]), "+f"(d[3])
        : "r"(a[0]), "r"(a[1]), "r"(a[2]), "r"(a[3]), "r"(b[0]), "r"(b[1]));
}
__device__ __forceinline__ u32 pack_bf16_hi(float a0, float a1) {
    __nv_bfloat16 h0 = __float2bfloat16(a0), h1 = __float2bfloat16(a1);
    return ((u32)__bfloat16_as_ushort(h1) << 16) | __bfloat16_as_ushort(h0);
}
__device__ __forceinline__ u32 pack_bf16_lo(float a0, float a1) {
    __nv_bfloat16 h0 = __float2bfloat16(a0), h1 = __float2bfloat16(a1);
    __nv_bfloat16 l0 = __float2bfloat16(a0 - __bfloat162float(h0));
    __nv_bfloat16 l1 = __float2bfloat16(a1 - __bfloat162float(h1));
    return ((u32)__bfloat16_as_ushort(l1) << 16) | __bfloat16_as_ushort(l0);
}
__device__ __forceinline__ double vload(const double* p) {
    return *(volatile const double*)p;
}
__device__ __forceinline__ void grid_barrier() {
    __syncthreads();
    if (threadIdx.x == 0) {
        __threadfence();
        u32 gen = *(volatile u32*)&g_barg;
        u32 old = atomicAdd(&g_barc, 1);
        if (old == gridDim.x - 1) {
            atomicExch(&g_barc, 0);
            __threadfence();
            atomicExch(&g_barg, gen + 1);
        } else {
            while (*(volatile u32*)&g_barg == gen) { __nanosleep(128); }
        }
        __threadfence();
    }
    __syncthreads();
}

// ---------------- smem layout -------------------------------------------------
#define O_WH   0                    // 45056
#define O_WL   45056                // 45056
#define O_AH   90112                // 11264
#define O_AL   101376               // 11264
#define O_BIAS 112640               // 1024
#define O_FOLD 113664               // 192
#define O_HPW  113856               // 16*69*4 = 4416
#define O_SCSH 118272               // sc[16], sh[16], b1[16] = 192
#define O_LAST 118464               // 14*64*8 = 7168
#define O_RED  125632               // 16*32*4 = 2048
#define LSTM_SMEM 127680

// ---------------- prep: fold se_W2/se_b2 into Wih; bf16-split; zero stats ----
__global__ void k_prep(const float* __restrict__ Wih, const float* __restrict__ Whh,
                       const float* __restrict__ bih, const float* __restrict__ bhh,
                       const float* __restrict__ seW2, const float* __restrict__ seb2) {
    int gc = threadIdx.x;
    if (gc < 5) g_enc_stats[gc] = 0.0;
    if (gc < 10) ((double*)g_se2)[gc] = 0.0;
    if (gc < 64) ((double*)g_hp2)[gc] = 0.0;
    float wr[64];
#pragma unroll 8
    for (int m = 0; m < 64; m++) wr[m] = Wih[gc * 64 + m];
    float be = bih[gc] + bhh[gc];
#pragma unroll 8
    for (int m = 0; m < 64; m++) be += wr[m] * seb2[m];
    g_bias[gc] = be;
    for (int k = 0; k < WSTR; k++) {
        float w = 0.f;
        if (k < 16) {
#pragma unroll 8
            for (int m = 0; m < 64; m++) w += wr[m] * seW2[m * 16 + k];
        } else if (k < 80) {
            w = Whh[gc * 64 + (k - 16)];
        }
        __nv_bfloat16 hi = __float2bfloat16(w);
        __nv_bfloat16 lo = __float2bfloat16(w - __bfloat162float(hi));
        g_Wh[gc * WSTR + k] = hi;
        g_Wl[gc * WSTR + k] = lo;
    }
}

// ---------------- moments of normalized obs + init last_pos -----------------
__global__ void k_moments(const float* __restrict__ obs, const void* pxm, const void* pym,
                          int TB, int B) {
    __shared__ float red[8][5];
    float invx = 1.0f / scalar_f(pxm), invy = 1.0f / scalar_f(pym);
    int idx = blockIdx.x * blockDim.x + threadIdx.x;
    int stride = gridDim.x * blockDim.x;
    float s[5] = {0, 0, 0, 0, 0};
    for (int i = idx; i < TB; i += stride) {
        float x = obs[2 * i] * invx, y = obs[2 * i + 1] * invy;
        s[0] += x; s[1] += y; s[2] += x * x; s[3] += y * y; s[4] += x * y;
    }
    int wid = threadIdx.x >> 5, lane = threadIdx.x & 31;
#pragma unroll
    for (int k = 0; k < 5; k++) s[k] = wred(s[k]);
    if (lane == 0) {
#pragma unroll
        for (int k = 0; k < 5; k++) red[wid][k] = s[k];
    }
    __syncthreads();
    if (wid == 0 && lane < 5) {
        float t = 0.f;
#pragma unroll
        for (int w = 0; w < 8; w++) t += red[w][lane];
        atomicAdd(&g_enc_stats[lane], (double)t);
    }
    int off = TB - B;
    for (int i = idx; i < B; i += stride) {
        g_last[2 * i]     = obs[2 * (off + i)]     * invx;
        g_last[2 * i + 1] = obs[2 * (off + i) + 1] * invy;
    }
}

// z-projection of h (from smem A-buffer, ALL 64 values) + stats accumulation.
#define ZPROJ(row0_, hp4_)                                                        \
    {                                                                             \
        const float* Wp_ = (const float*)(sm + O_HPW);                            \
        const float* b1s_ = ((const float*)(sm + O_SCSH)) + 32;                   \
        const uint4* ahp_ = (const uint4*)(sm + O_AH + srow * (WSTR * 2) + 32);   \
        const uint4* alp_ = (const uint4*)(sm + O_AL + srow * (WSTR * 2) + 32);   \
        float z0_ = b1s_[j2], z1_ = b1s_[j2 + 1];                                 \
        const float* w0p_ = Wp_ + j2 * 69;                                        \
        const float* w1p_ = Wp_ + (j2 + 1) * 69;                                  \
        _Pragma("unroll")                                                         \
        for (int w4_ = 0; w4_ < 8; w4_++) {                                       \
            uint4 hi_ = ahp_[w4_], lo_ = alp_[w4_];                               \
            u32 hs_[4] = {hi_.x, hi_.y, hi_.z, hi_.w};                            \
            u32 ls_[4] = {lo_.x, lo_.y, lo_.z, lo_.w};                            \
            _Pragma("unroll")                                                     \
            for (int e_ = 0; e_ < 4; e_++) {                                      \
                float2 a_ = __bfloat1622float2(*(__nv_bfloat162*)&hs_[e_]);       \
                float2 b_ = __bfloat1622float2(*(__nv_bfloat162*)&ls_[e_]);       \
                float h0_ = a_.x + b_.x, h1_ = a_.y + b_.y;                       \
                int k_ = w4_ * 8 + e_ * 2;                                        \
                z0_ += h0_ * w0p_[k_] + h1_ * w0p_[k_ + 1];                       \
                z1_ += h0_ * w1p_[k_] + h1_ * w1p_[k_ + 1];                       \
            }                                                                     \
        }                                                                         \
        int rz_ = (row0_) + srow;                                                 \
        *(float2*)(g_z + (size_t)rz_ * 16 + j2) = make_float2(z0_, z1_);          \
        hp4_[0] += z0_; hp4_[1] += z1_;                                           \
        hp4_[2] += z0_ * z0_; hp4_[3] += z1_ * z1_;                               \
    }

#define HP_REDUCE(dstpar_)                                                        \
    {                                                                             \
        _Pragma("unroll")                                                         \
        for (int k_ = 0; k_ < 4; k_++) {                                          \
            hp4[k_] += __shfl_xor_sync(0xffffffffu, hp4[k_], 8);                  \
            hp4[k_] += __shfl_xor_sync(0xffffffffu, hp4[k_], 16);                 \
        }                                                                         \
        float* red_ = (float*)(sm + O_RED);                                       \
        __syncthreads();                                                          \
        if (lane < 8) {                                                           \
            red_[wid * 32 + j2] = hp4[0];                                         \
            red_[wid * 32 + j2 + 1] = hp4[1];                                     \
            red_[wid * 32 + 16 + j2] = hp4[2];                                    \
            red_[wid * 32 + 17 + j2] = hp4[3];                                    \
        }                                                                         \
        __syncthreads();                                                          \
        if (tid < 32) {                                                           \
            float tot_ = 0.f;                                                     \
            for (int w_ = 0; w_ < 16; w_++) tot_ += red_[w_ * 32 + tid];          \
            atomicAdd(&g_hp2[dstpar_][tid], (double)tot_);                        \
        }                                                                         \
    }

// ======================= fused 8-step encoder ================================
__global__ void __launch_bounds__(512, 1)
k_enc(const float* __restrict__ obs, int B, int nTiles,
      const float* __restrict__ seW1, const float* __restrict__ seb1,
      const float* __restrict__ seg_, const float* __restrict__ seb_,
      const float* __restrict__ hpW1, const float* __restrict__ hpb1,
      const void* pxm, const void* pym, float Ninv) {
    extern __shared__ char sm[];
    float* bs = (float*)(sm + O_BIAS);
    float* fold = (float*)(sm + O_FOLD);
    u32 smb = smem_u32(sm);
    int tid = threadIdx.x, wid = tid >> 5, lane = tid & 31;

    {
        const float4* s1 = (const float4*)g_Wh;
        const float4* s2 = (const float4*)g_Wl;
        float4* d1 = (float4*)(sm + O_WH);
        float4* d2 = (float4*)(sm + O_WL);
        for (int i = tid; i < 2816; i += 512) { d1[i] = s1[i]; d2[i] = s2[i]; }
    }
    if (tid < 256) bs[tid] = g_bias[tid];
    {   // stage hpW1 (pad 69) + b1
        float* Wp = (float*)(sm + O_HPW);
        for (int i = tid; i < 1024; i += 512) { int j = i >> 6, k = i & 63; Wp[j * 69 + k] = hpW1[i]; }
        if (tid < 16) (((float*)(sm + O_SCSH)) + 32)[tid] = hpb1[tid];
    }
    if (tid < 16) {   // encode BN fold (analytic)
        const double* st = g_enc_stats;
        double mx = st[0] * Ninv, my = st[1] * Ninv;
        double vxx = st[2] * Ninv - mx * mx;
        double vyy = st[3] * Ninv - my * my;
        double cxy = st[4] * Ninv - mx * my;
        float w0 = seW1[2 * tid], w1 = seW1[2 * tid + 1];
        float mu = (float)(w0 * mx + w1 * my) + seb1[tid];
        float var = (float)((double)w0 * w0 * vxx + (double)w1 * w1 * vyy +
                            2.0 * (double)w0 * w1 * cxy);
        float sc = seg_[tid] * rsqrtf(var + EPSBN);
        float ix = 1.f / scalar_f(pxm), iy = 1.f / scalar_f(pym);
        fold[tid]      = w0 * sc * ix;
        fold[16 + tid] = w1 * sc * iy;
        fold[32 + tid] = (seb1[tid] - mu) * sc + seb_[tid];
    }
    __syncthreads();

    int wm = wid & 1, wn = wid >> 1;
    int j0 = wn * 8 + (lane & 3) * 2;
    float bj[4][2];
#pragma unroll
    for (int g = 0; g < 4; g++) { bj[g][0] = bs[g * 64 + j0]; bj[g][1] = bs[g * 64 + j0 + 1]; }

    u32 bh[3][4][2];
    {
        u32 nrow = (u32)(wn * 8 + (lane & 7));
        u32 gsel = (u32)(((lane >> 4) & 1) * 64);
        u32 ksel = (u32)(((lane >> 3) & 1) * 16);
#pragma unroll
        for (int kt = 0; kt < 3; kt++) {
#pragma unroll
            for (int p = 0; p < 2; p++) {
                u32 r4[4];
                ldsm4(r4, smb + O_WH +
                      ((u32)(p * 2) * 64 + gsel + nrow) * (WSTR * 2) + ksel + (u32)(kt * 32));
                bh[kt][2 * p][0] = r4[0]; bh[kt][2 * p][1] = r4[1];
                bh[kt][2 * p + 1][0] = r4[2]; bh[kt][2 * p + 1][1] = r4[3];
            }
        }
    }

    u32 aRowOff = (u32)((wm * 32 + (lane & 15)) * (WSTR * 2));
    u32 aColSel = (u32)(((lane >> 4) & 1) * 16);
    u32 bRow = (u32)(wn * 8 + (lane & 7));
    u32 bGsel = (u32)(((lane >> 4) & 1) * 64);
    u32 bKsel = (u32)(((lane >> 3) & 1) * 16);
    int srow = tid >> 3, seg = tid & 7, j2 = seg * 2;
    float fa0 = fold[j2], fb0 = fold[16 + j2], fc0 = fold[32 + j2];
    float fa1 = fold[j2 + 1], fb1 = fold[16 + j2 + 1], fc1 = fold[32 + j2 + 1];

    float hp4[4] = {0, 0, 0, 0};

    for (int tile = blockIdx.x; tile < nTiles; tile += gridDim.x) {
        int row0 = tile * 64;
        {
            float x = obs[2 * (size_t)(row0 + srow)];
            float y = obs[2 * (size_t)(row0 + srow) + 1];
            float f0 = fmaxf(fa0 * x + fb0 * y + fc0, 0.f);
            float f1 = fmaxf(fa1 * x + fb1 * y + fc1, 0.f);
            int off = srow * (WSTR * 2) + j2 * 2;
            *(u32*)(sm + O_AH + off) = pack_bf16_hi(f0, f1);
            *(u32*)(sm + O_AL + off) = pack_bf16_lo(f0, f1);
        }
        float creg[2][2][2];

        for (int t = 0; t < T_OBS; t++) {
            __syncthreads();
            float acc[2][4][4];
#pragma unroll
            for (int mt = 0; mt < 2; mt++)
#pragma unroll
                for (int g = 0; g < 4; g++)
#pragma unroll
                    for (int e = 0; e < 4; e++) acc[mt][g][e] = 0.f;
            int nkt = t ? 5 : 1;
#pragma unroll
            for (int kt = 0; kt < 5; kt++) {
                if (kt >= nkt) break;
                u32 kOff = (u32)(kt * 32);
                u32 ah0[4], ah1[4], al0[4], al1[4];
                u32 aAddr = smb + O_AH + aRowOff + aColSel + kOff;
                ldsm4(ah0, aAddr);
                ldsm4(ah1, aAddr + 16 * (WSTR * 2));
                u32 aAddrL = smb + O_AL + aRowOff + aColSel + kOff;
                ldsm4(al0, aAddrL);
                ldsm4(al1, aAddrL + 16 * (WSTR * 2));
                u32 bl[4][2];
#pragma unroll
                for (int p = 0; p < 2; p++) {
                    u32 r4[4];
                    ldsm4(r4, smb + O_WL +
                          ((u32)(p * 2) * 64 + bGsel + bRow) * (WSTR * 2) + bKsel + kOff);
                    bl[2 * p][0] = r4[0]; bl[2 * p][1] = r4[1];
                    bl[2 * p + 1][0] = r4[2]; bl[2 * p + 1][1] = r4[3];
                }
                if (kt < 3) {
#pragma unroll
                    for (int g = 0; g < 4; g++) {
                        mma16816(acc[0][g], ah0, bh[kt][g]);
                        mma16816(acc[1][g], ah1, bh[kt][g]);
                        mma16816(acc[0][g], al0, bh[kt][g]);
                        mma16816(acc[1][g], al1, bh[kt][g]);
                        mma16816(acc[0][g], ah0, bl[g]);
                        mma16816(acc[1][g], ah1, bl[g]);
                    }
                } else {
                    u32 bhd[4][2];
#pragma unroll
                    for (int p = 0; p < 2; p++) {
                        u32 r4[4];
                        ldsm4(r4, smb + O_WH +
                              ((u32)(p * 2) * 64 + bGsel + bRow) * (WSTR * 2) + bKsel + kOff);
                        bhd[2 * p][0] = r4[0]; bhd[2 * p][1] = r4[1];
                        bhd[2 * p + 1][0] = r4[2]; bhd[2 * p + 1][1] = r4[3];
                    }
#pragma unroll
                    for (int g = 0; g < 4; g++) {
                        mma16816(acc[0][g], ah0, bhd[g]);
                        mma16816(acc[1][g], ah1, bhd[g]);
                        mma16816(acc[0][g], al0, bhd[g]);
                        mma16816(acc[1][g], al1, bhd[g]);
                        mma16816(acc[0][g], ah0, bl[g]);
                        mma16816(acc[1][g], ah1, bl[g]);
                    }
                }
            }

            float hn[2][2][2];
#pragma unroll
            for (int mt = 0; mt < 2; mt++)
#pragma unroll
                for (int rr = 0; rr < 2; rr++)
#pragma unroll
                    for (int cc = 0; cc < 2; cc++) {
                        int e = rr * 2 + cc;
                        float iv = acc[mt][0][e] + bj[0][cc];
                        float fv = acc[mt][1][e] + bj[1][cc];
                        float gv = acc[mt][2][e] + bj[2][cc];
                        float ov = acc[mt][3][e] + bj[3][cc];
                        float cold = t ? creg[mt][rr][cc] : 0.f;
                        float cnew = fast_sig(fv) * cold + fast_sig(iv) * fast_tanh(gv);
                        creg[mt][rr][cc] = cnew;
                        hn[mt][rr][cc] = fast_sig(ov) * fast_tanh(cnew);
                    }
            __syncthreads();

            // write h into A-buffer (needed for next step's MMA / final z-proj)
#pragma unroll
            for (int mt = 0; mt < 2; mt++)
#pragma unroll
                for (int rr = 0; rr < 2; rr++) {
                    int lrow = wm * 32 + mt * 16 + rr * 8 + (lane >> 2);
                    int off = lrow * (WSTR * 2) + (16 + j0) * 2;
                    *(u32*)(sm + O_AH + off) = pack_bf16_hi(hn[mt][rr][0], hn[mt][rr][1]);
                    *(u32*)(sm + O_AL + off) = pack_bf16_lo(hn[mt][rr][0], hn[mt][rr][1]);
                }

            if (t == T_OBS - 1) {
#pragma unroll
                for (int mt = 0; mt < 2; mt++)
#pragma unroll
                    for (int rr = 0; rr < 2; rr++) {
                        int r = row0 + wm * 32 + mt * 16 + rr * 8 + (lane >> 2);
                        *(float2*)(g_h + (size_t)r * 64 + j0) =
                            make_float2(hn[mt][rr][0], hn[mt][rr][1]);
                        *(float2*)(g_c + (size_t)r * 64 + j0) =
                            make_float2(creg[mt][rr][0], creg[mt][rr][1]);
                    }
                __syncthreads();
                ZPROJ(row0, hp4);
            } else {
                const float* xyt = obs + (size_t)(t + 1) * B * 2;
                float x = xyt[2 * (size_t)(row0 + srow)];
                float y = xyt[2 * (size_t)(row0 + srow) + 1];
                float f0 = fmaxf(fa0 * x + fb0 * y + fc0, 0.f);
                float f1 = fmaxf(fa1 * x + fb1 * y + fc1, 0.f);
                int off = srow * (WSTR * 2) + j2 * 2;
                *(u32*)(sm + O_AH + off) = pack_bf16_hi(f0, f1);
                *(u32*)(sm + O_AL + off) = pack_bf16_lo(f0, f1);
            }
        }
        __syncthreads();
    }
    HP_REDUCE(0);
}

// ======================= decode step: pos + barrier + LSTM + zproj ===========
__global__ void __launch_bounds__(512, 1)
k_dec(int s, int B, int nTiles, float* __restrict__ out,
      const float* __restrict__ seW1, const float* __restrict__ seb1,
      const float* __restrict__ seg_, const float* __restrict__ seb_,
      const float* __restrict__ hpW1, const float* __restrict__ hpb1,
      const float* __restrict__ hpg, const float* __restrict__ hpb,
      const float* __restrict__ hpW2, const float* __restrict__ hpb2,
      const void* pxm, const void* pym, float Binv, int doLSTM) {
    extern __shared__ char sm[];
    float* bs = (float*)(sm + O_BIAS);
    float* fold = (float*)(sm + O_FOLD);
    float* scp = (float*)(sm + O_SCSH);        // sc[16], sh[16], b1[16]
    float2* slast = (float2*)(sm + O_LAST);
    u32 smb = smem_u32(sm);
    int tid = threadIdx.x, wid = tid >> 5, lane = tid & 31;
    int par = s & 1;

    {
        const float4* s1 = (const float4*)g_Wh;
        const float4* s2 = (const float4*)g_Wl;
        float4* d1 = (float4*)(sm + O_WH);
        float4* d2 = (float4*)(sm + O_WL);
        for (int i = tid; i < 2816; i += 512) { d1[i] = s1[i]; d2[i] = s2[i]; }
    }
    if (tid < 256) bs[tid] = g_bias[tid];
    {
        float* Wp = (float*)(sm + O_HPW);
        for (int i = tid; i < 1024; i += 512) { int j = i >> 6, k = i & 63; Wp[j * 69 + k] = hpW1[i]; }
    }
    if (tid < 16) {   // hidden2pos BN from stats of previous launch
        double mu = vload(&g_hp2[par][tid]) * Binv;
        double var = vload(&g_hp2[par][16 + tid]) * Binv - mu * mu;
        float s_ = hpg[tid] * rsqrtf((float)var + EPSBN);
        scp[tid] = s_;
        scp[16 + tid] = hpb[tid] - (float)mu * s_;
        scp[32 + tid] = hpb1[tid];
    }
    __syncthreads();

    float xmax = scalar_f(pxm), ymax = scalar_f(pym);
    int srow = tid >> 3, seg = tid & 7, j2 = seg * 2;

    // ---------- phase 1: positions, out, last cache, se moments ----------
    float se[5] = {0, 0, 0, 0, 0};
    {
        float w2x0 = __ldg(hpW2 + j2), w2x1 = __ldg(hpW2 + j2 + 1);
        float w2y0 = __ldg(hpW2 + 16 + j2), w2y1 = __ldg(hpW2 + 16 + j2 + 1);
        float b2x = __ldg(hpb2), b2y = __ldg(hpb2 + 1);
        float sc0 = scp[j2], sh0 = scp[16 + j2];
        float sc1 = scp[j2 + 1], sh1 = scp[16 + j2 + 1];
        int ti = 0;
        for (int tile = blockIdx.x; tile < nTiles; tile += gridDim.x, ti++) {
            int r = tile * 64 + srow;
            float2 z2 = *(const float2*)(g_z + (size_t)r * 16 + j2);
            float t0 = fmaxf(z2.x * sc0 + sh0, 0.f);
            float t1 = fmaxf(z2.y * sc1 + sh1, 0.f);
            float px = t0 * w2x0 + t1 * w2x1;
            float py = t0 * w2y0 + t1 * w2y1;
#pragma unroll
            for (int o = 1; o < 8; o <<= 1) {
                px += __shfl_xor_sync(0xffffffffu, px, o);
                py += __shfl_xor_sync(0xffffffffu, py, o);
            }
            if (seg == 0) {
                float lx = fast_sig(px + b2x + g_last[2 * (size_t)r]);
                float ly = fast_sig(py + b2y + g_last[2 * (size_t)r + 1]);
                g_last[2 * (size_t)r] = lx;
                g_last[2 * (size_t)r + 1] = ly;
                out[2 * (size_t)r] = lx * xmax;
                out[2 * (size_t)r + 1] = ly * ymax;
                slast[ti * 64 + srow] = make_float2(lx, ly);
                se[0] += lx; se[1] += ly; se[2] += lx * lx; se[3] += ly * ly; se[4] += lx * ly;
            }
        }
    }
    if (!doLSTM) return;

    {   // block-reduce se moments -> global
        float* red = (float*)(sm + O_RED);
#pragma unroll
        for (int k = 0; k < 5; k++) se[k] = wred(se[k]);
        if (lane == 0) {
#pragma unroll
            for (int k = 0; k < 5; k++) red[wid * 32 + k] = se[k];
        }
        __syncthreads();
        if (wid == 0 && lane < 5) {
            float t = 0.f;
#pragma unroll
            for (int w = 0; w < 16; w++) t += red[w * 32 + lane];
            atomicAdd(&g_se2[par][lane], (double)t);
            __threadfence();
        }
    }

    grid_barrier();

    if (blockIdx.x == 0) {   // recycle parity buffers for future launches
        if (tid < 32) *(volatile double*)&g_hp2[par][tid] = 0.0;
        if (tid < 5)  *(volatile double*)&g_se2[par ^ 1][tid] = 0.0;
    }
    if (tid < 16) {   // spatial-embedding BN fold from fresh se moments
        double mx = vload(&g_se2[par][0]) * Binv, my = vload(&g_se2[par][1]) * Binv;
        double vxx = vload(&g_se2[par][2]) * Binv - mx * mx;
        double vyy = vload(&g_se2[par][3]) * Binv - my * my;
        double cxy = vload(&g_se2[par][4]) * Binv - mx * my;
        float w0 = seW1[2 * tid], w1 = seW1[2 * tid + 1];
        float mu = (float)(w0 * mx + w1 * my) + seb1[tid];
        float var = (float)((double)w0 * w0 * vxx + (double)w1 * w1 * vyy +
                            2.0 * (double)w0 * w1 * cxy);
        float sc = seg_[tid] * rsqrtf(var + EPSBN);
        fold[tid]      = w0 * sc;
        fold[16 + tid] = w1 * sc;
        fold[32 + tid] = (seb1[tid] - mu) * sc + seb_[tid];
    }
    __syncthreads();

    // ---------- phase 2: LSTM + z-projection ----------
    int wm = wid & 1, wn = wid >> 1;
    int j0 = wn * 8 + (lane & 3) * 2;
    float bj[4][2];
#pragma unroll
    for (int g = 0; g < 4; g++) { bj[g][0] = bs[g * 64 + j0]; bj[g][1] = bs[g * 64 + j0 + 1]; }

    u32 bh[5][4][2];
    {
        u32 nrow = (u32)(wn * 8 + (lane & 7));
        u32 gsel = (u32)(((lane >> 4) & 1) * 64);
        u32 ksel = (u32)(((lane >> 3) & 1) * 16);
#pragma unroll
        for (int kt = 0; kt < 5; kt++) {
#pragma unroll
            for (int p = 0; p < 2; p++) {
                u32 r4[4];
                ldsm4(r4, smb + O_WH +
                      ((u32)(p * 2) * 64 + gsel + nrow) * (WSTR * 2) + ksel + (u32)(kt * 32));
                bh[kt][2 * p][0] = r4[0]; bh[kt][2 * p][1] = r4[1];
                bh[kt][2 * p + 1][0] = r4[2]; bh[kt][2 * p + 1][1] = r4[3];
            }
        }
    }

    u32 aRowOff = (u32)((wm * 32 + (lane & 15)) * (WSTR * 2));
    u32 aColSel = (u32)(((lane >> 4) & 1) * 16);
    u32 bRow = (u32)(wn * 8 + (lane & 7));
    u32 bGsel = (u32)(((lane >> 4) & 1) * 64);
    u32 bKsel = (u32)(((lane >> 3) & 1) * 16);
    float fa0 = fold[j2], fb0 = fold[16 + j2], fc0 = fold[32 + j2];
    float fa1 = fold[j2 + 1], fb1 = fold[16 + j2 + 1], fc1 = fold[32 + j2 + 1];

    float hp4[4] = {0, 0, 0, 0};
    int ti = 0;
    for (int tile = blockIdx.x; tile < nTiles; tile += gridDim.x, ti++) {
        int row0 = tile * 64;
        {   // stage h (coalesced) + feats from smem last cache
            int r = row0 + srow;
            const float4* hp = (const float4*)(g_h + (size_t)r * 64 + seg * 8);
            float4 h0 = hp[0], h1 = hp[1];
            uint4 hi, lo;
            hi.x = pack_bf16_hi(h0.x, h0.y); lo.x = pack_bf16_lo(h0.x, h0.y);
            hi.y = pack_bf16_hi(h0.z, h0.w); lo.y = pack_bf16_lo(h0.z, h0.w);
            hi.z = pack_bf16_hi(h1.x, h1.y); lo.z = pack_bf16_lo(h1.x, h1.y);
            hi.w = pack_bf16_hi(h1.z, h1.w); lo.w = pack_bf16_lo(h1.z, h1.w);
            int off = srow * (WSTR * 2) + 32 + seg * 16;
            *(uint4*)(sm + O_AH + off) = hi;
            *(uint4*)(sm + O_AL + off) = lo;
            float2 lp = slast[ti * 64 + srow];
            float f0 = fmaxf(fa0 * lp.x + fb0 * lp.y + fc0, 0.f);
            float f1 = fmaxf(fa1 * lp.x + fb1 * lp.y + fc1, 0.f);
            int offf = srow * (WSTR * 2) + j2 * 2;
            *(u32*)(sm + O_AH + offf) = pack_bf16_hi(f0, f1);
            *(u32*)(sm + O_AL + offf) = pack_bf16_lo(f0, f1);
        }
        __syncthreads();

        float acc[2][4][4];
#pragma unroll
        for (int mt = 0; mt < 2; mt++)
#pragma unroll
            for (int g = 0; g < 4; g++)
#pragma unroll
                for (int e = 0; e < 4; e++) acc[mt][g][e] = 0.f;

#pragma unroll
        for (int kt = 0; kt < 5; kt++) {
            u32 kOff = (u32)(kt * 32);
            u32 ah0[4], ah1[4], al0[4], al1[4];
            u32 aAddr = smb + O_AH + aRowOff + aColSel + kOff;
            ldsm4(ah0, aAddr);
            ldsm4(ah1, aAddr + 16 * (WSTR * 2));
            u32 aAddrL = smb + O_AL + aRowOff + aColSel + kOff;
            ldsm4(al0, aAddrL);
            ldsm4(al1, aAddrL + 16 * (WSTR * 2));
            u32 bl[4][2];
#pragma unroll
            for (int p = 0; p < 2; p++) {
                u32 r4[4];
                ldsm4(r4, smb + O_WL +
                      ((u32)(p * 2) * 64 + bGsel + bRow) * (WSTR * 2) + bKsel + kOff);
                bl[2 * p][0] = r4[0]; bl[2 * p][1] = r4[1];
                bl[2 * p + 1][0] = r4[2]; bl[2 * p + 1][1] = r4[3];
            }
#pragma unroll
            for (int g = 0; g < 4; g++) {
                mma16816(acc[0][g], ah0, bh[kt][g]);
                mma16816(acc[1][g], ah1, bh[kt][g]);
                mma16816(acc[0][g], al0, bh[kt][g]);
                mma16816(acc[1][g], al1, bh[kt][g]);
                mma16816(acc[0][g], ah0, bl[g]);
                mma16816(acc[1][g], ah1, bl[g]);
            }
        }

        float hn[2][2][2];
#pragma unroll
        for (int mt = 0; mt < 2; mt++)
#pragma unroll
            for (int rr = 0; rr < 2; rr++) {
                int rw = row0 + wm * 32 + mt * 16 + rr * 8 + (lane >> 2);
                float2 c2 = *(float2*)(g_c + (size_t)rw * 64 + j0);
#pragma unroll
                for (int cc = 0; cc < 2; cc++) {
                    int e = rr * 2 + cc;
                    float iv = acc[mt][0][e] + bj[0][cc];
                    float fv = acc[mt][1][e] + bj[1][cc];
                    float gv = acc[mt][2][e] + bj[2][cc];
                    float ov = acc[mt][3][e] + bj[3][cc];
                    float cold = cc ? c2.y : c2.x;
                    float cnew = fast_sig(fv) * cold + fast_sig(iv) * fast_tanh(gv);
                    (cc ? c2.y : c2.x) = cnew;
                    hn[mt][rr][cc] = fast_sig(ov) * fast_tanh(cnew);
                }
                *(float2*)(g_c + (size_t)rw * 64 + j0) = c2;
                *(float2*)(g_h + (size_t)rw * 64 + j0) = make_float2(hn[mt][rr][0], hn[mt][rr][1]);
            }
        __syncthreads();   // all ldmatrix reads done

        // h_new into A-buffer for z-projection
#pragma unroll
        for (int mt = 0; mt < 2; mt++)
#pragma unroll
            for (int rr = 0; rr < 2; rr++) {
                int lrow = wm * 32 + mt * 16 + rr * 8 + (lane >> 2);
                int off = lrow * (WSTR * 2) + (16 + j0) * 2;
                *(u32*)(sm + O_AH + off) = pack_bf16_hi(hn[mt][rr][0], hn[mt][rr][1]);
                *(u32*)(sm + O_AL + off) = pack_bf16_lo(hn[mt][rr][0], hn[mt][rr][1]);
            }
        __syncthreads();
        ZPROJ(row0, hp4);
        __syncthreads();
    }
    HP_REDUCE(par ^ 1);
}

// ---------------- launch ------------------------------------------------------
extern "C" void kernel_launch(void* const* d_in, const int* in_sizes, int n_in,
                              void* d_out, int out_size) {
    const float* obs  = (const float*)d_in[0];
    const float* seW1 = (const float*)d_in[1];
    const float* seb1 = (const float*)d_in[2];
    const float* seg  = (const float*)d_in[3];
    const float* seb  = (const float*)d_in[4];
    const float* seW2 = (const float*)d_in[5];
    const float* seb2 = (const float*)d_in[6];
    const float* hpW1 = (const float*)d_in[7];
    const float* hpb1 = (const float*)d_in[8];
    const float* hpg  = (const float*)d_in[9];
    const float* hpb  = (const float*)d_in[10];
    const float* hpW2 = (const float*)d_in[11];
    const float* hpb2 = (const float*)d_in[12];
    const float* Wih  = (const float*)d_in[13];
    const float* Whh  = (const float*)d_in[14];
    const float* bih  = (const float*)d_in[15];
    const float* bhh  = (const float*)d_in[16];
    const void*  pxm  = d_in[17];
    const void*  pym  = d_in[18];

    int B = in_sizes[0] / (T_OBS * 2);
    int TB = T_OBS * B;
    int predLen = out_size / (2 * B);
    float* out = (float*)d_out;
    int nTiles = B / 64;

    cudaFuncSetAttribute(k_enc, cudaFuncAttributeMaxDynamicSharedMemorySize, LSTM_SMEM);
    cudaFuncSetAttribute(k_dec, cudaFuncAttributeMaxDynamicSharedMemorySize, LSTM_SMEM);

    k_prep<<<1, 256>>>(Wih, Whh, bih, bhh, seW2, seb2);
    k_moments<<<512, 256>>>(obs, pxm, pym, TB, B);
    k_enc<<<148, 512, LSTM_SMEM>>>(obs, B, nTiles, seW1, seb1, seg, seb,
                                   hpW1, hpb1, pxm, pym, 1.0f / (float)TB);

    for (int s = 0; s < predLen; s++) {
        k_dec<<<148, 512, LSTM_SMEM>>>(s, B, nTiles, out + (size_t)s * B * 2,
                                       seW1, seb1, seg, seb,
                                       hpW1, hpb1, hpg, hpb, hpW2, hpb2,
                                       pxm, pym, 1.0f / (float)B,
                                       (s + 1 < predLen) ? 1 : 0);
    }
}

// round 9
// speedup vs baseline: 1.1262x; 1.1262x over previous
#include <cuda_runtime.h>
#include <cuda_bf16.h>
#include <math.h>

#define T_OBS 8
#define EPSBN 1e-5f

typedef unsigned int u32;
typedef unsigned long long u64;

#define MAXB 131072
#define WSTR 88   // padded k-stride (bf16): 176B rows, conflict-free ldmatrix

// ---------------- static device scratch ------------------------------------
__device__ float  g_h[MAXB * 64];
__device__ float  g_c[MAXB * 64];
__device__ float  g_z[MAXB * 16];
__device__ float  g_last[MAXB * 2];
__device__ __align__(16) __nv_bfloat16 g_Wh[256 * WSTR];
__device__ __align__(16) __nv_bfloat16 g_Wl[256 * WSTR];
__device__ float  g_bias[256];
__device__ double g_enc_stats[5];
__device__ double g_se_stats[5];
__device__ double g_hp_stats[32];

// ---------------- helpers ----------------------------------------------------
__device__ __forceinline__ float scalar_f(const void* p) {
    int iv = *(const int*)p;
    float fv = __int_as_float(iv);
    if (fv >= 1e-3f && fv <= 1e7f) return fv;
    return (float)iv;
}
__device__ __forceinline__ float fast_sig(float x) {
    float t; asm("ex2.approx.f32 %0, %1;" : "=f"(t) : "f"(-1.4426950408889634f * x));
    float r; asm("rcp.approx.f32 %0, %1;" : "=f"(r) : "f"(1.0f + t));
    return r;
}
// fused LSTM pointwise: 8 MUFU per cell instead of 10
__device__ __forceinline__ void lstm_cell(float iv, float fv, float gv, float ov,
                                          float cold, float& cnew, float& hnew) {
    gv = fminf(fmaxf(gv, -30.f), 30.f);
    float tf; asm("ex2.approx.f32 %0, %1;" : "=f"(tf) : "f"(-1.4426950408889634f * fv));
    float sf; asm("rcp.approx.f32 %0, %1;" : "=f"(sf) : "f"(1.0f + tf));
    float ei; asm("ex2.approx.f32 %0, %1;" : "=f"(ei) : "f"(-1.4426950408889634f * iv));
    float eg; asm("ex2.approx.f32 %0, %1;" : "=f"(eg) : "f"(2.8853900817779268f * gv));
    float dig = (1.0f + ei) * (eg + 1.0f);
    float rig; asm("rcp.approx.f32 %0, %1;" : "=f"(rig) : "f"(dig));
    float c2 = sf * cold + (eg - 1.0f) * rig;
    cnew = c2;
    float eo; asm("ex2.approx.f32 %0, %1;" : "=f"(eo) : "f"(-1.4426950408889634f * ov));
    float ec; asm("ex2.approx.f32 %0, %1;" : "=f"(ec) : "f"(2.8853900817779268f * c2));
    float doc = (1.0f + eo) * (ec + 1.0f);
    float roc; asm("rcp.approx.f32 %0, %1;" : "=f"(roc) : "f"(doc));
    hnew = (ec - 1.0f) * roc;
}
__device__ __forceinline__ float wred(float v) {
#pragma unroll
    for (int o = 16; o > 0; o >>= 1) v += __shfl_down_sync(0xffffffffu, v, o);
    return v;
}
__device__ __forceinline__ u32 smem_u32(const void* p) {
    u32 a;
    asm("{ .reg .u64 t; cvta.to.shared.u64 t, %1; cvt.u32.u64 %0, t; }" : "=r"(a) : "l"(p));
    return a;
}
__device__ __forceinline__ void ldsm4(u32* r, u32 addr) {
    asm volatile("ldmatrix.sync.aligned.m8n8.x4.shared.b16 {%0,%1,%2,%3}, [%4];"
        : "=r"(r[0]), "=r"(r[1]), "=r"(r[2]), "=r"(r[3]) : "r"(addr));
}
__device__ __forceinline__ void mma16816(float* d, const u32* a, const u32* b) {
    asm volatile(
        "mma.sync.aligned.m16n8k16.row.col.f32.bf16.bf16.f32 "
        "{%0,%1,%2,%3},{%4,%5,%6,%7},{%8,%9},{%0,%1,%2,%3};"
        : "+f"(d[0]), "+f"(d[1]), "+f"(d[2]), "+f"(d[3])
        : "r"(a[0]), "r"(a[1]), "r"(a[2]), "r"(a[3]), "r"(b[0]), "r"(b[1]));
}
__device__ __forceinline__ u32 pack_bf16_hi(float a0, float a1) {
    __nv_bfloat16 h0 = __float2bfloat16(a0), h1 = __float2bfloat16(a1);
    return ((u32)__bfloat16_as_ushort(h1) << 16) | __bfloat16_as_ushort(h0);
}
__device__ __forceinline__ u32 pack_bf16_lo(float a0, float a1) {
    __nv_bfloat16 h0 = __float2bfloat16(a0), h1 = __float2bfloat16(a1);
    __nv_bfloat16 l0 = __float2bfloat16(a0 - __bfloat162float(h0));
    __nv_bfloat16 l1 = __float2bfloat16(a1 - __bfloat162float(h1));
    return ((u32)__bfloat16_as_ushort(l1) << 16) | __bfloat16_as_ushort(l0);
}

// ---------------- smem layout (double-buffered A) ----------------------------
#define O_WH   0                    // 45056
#define O_WL   45056                // 45056
#define O_AB0  90112                // AH0; AL0=+11264; AH1=+22528; AL1=+33792
#define O_BIAS 135168               // 1024
#define O_FOLD 136192               // 192
#define LSTM_SMEM 136448

// ---------------- prep: fold se_W2/se_b2 into Wih; bf16-split ---------------
__global__ void k_prep(const float* __restrict__ Wih, const float* __restrict__ Whh,
                       const float* __restrict__ bih, const float* __restrict__ bhh,
                       const float* __restrict__ seW2, const float* __restrict__ seb2) {
    int gc = threadIdx.x;
    if (gc < 5) g_enc_stats[gc] = 0.0;
    float wr[64];
#pragma unroll 8
    for (int m = 0; m < 64; m++) wr[m] = Wih[gc * 64 + m];
    float be = bih[gc] + bhh[gc];
#pragma unroll 8
    for (int m = 0; m < 64; m++) be += wr[m] * seb2[m];
    g_bias[gc] = be;
    for (int k = 0; k < WSTR; k++) {
        float w = 0.f;
        if (k < 16) {
#pragma unroll 8
            for (int m = 0; m < 64; m++) w += wr[m] * seW2[m * 16 + k];
        } else if (k < 80) {
            w = Whh[gc * 64 + (k - 16)];
        }
        __nv_bfloat16 hi = __float2bfloat16(w);
        __nv_bfloat16 lo = __float2bfloat16(w - __bfloat162float(hi));
        g_Wh[gc * WSTR + k] = hi;
        g_Wl[gc * WSTR + k] = lo;
    }
}

// ---------------- moments of normalized obs + init last_pos -----------------
__global__ void k_moments(const float* __restrict__ obs, const void* pxm, const void* pym,
                          int TB, int B) {
    __shared__ float red[8][5];
    float invx = 1.0f / scalar_f(pxm), invy = 1.0f / scalar_f(pym);
    int idx = blockIdx.x * blockDim.x + threadIdx.x;
    int stride = gridDim.x * blockDim.x;
    float s[5] = {0, 0, 0, 0, 0};
    for (int i = idx; i < TB; i += stride) {
        float x = obs[2 * i] * invx, y = obs[2 * i + 1] * invy;
        s[0] += x; s[1] += y; s[2] += x * x; s[3] += y * y; s[4] += x * y;
    }
    int wid = threadIdx.x >> 5, lane = threadIdx.x & 31;
#pragma unroll
    for (int k = 0; k < 5; k++) s[k] = wred(s[k]);
    if (lane == 0) {
#pragma unroll
        for (int k = 0; k < 5; k++) red[wid][k] = s[k];
    }
    __syncthreads();
    if (wid == 0 && lane < 5) {
        float t = 0.f;
#pragma unroll
        for (int w = 0; w < 8; w++) t += red[w][lane];
        atomicAdd(&g_enc_stats[lane], (double)t);
    }
    int off = TB - B;
    for (int i = idx; i < B; i += stride) {
        g_last[2 * i]     = obs[2 * (off + i)]     * invx;
        g_last[2 * i + 1] = obs[2 * (off + i) + 1] * invy;
    }
}

// ======================= fused 8-step encoder ================================
__global__ void __launch_bounds__(512, 1)
k_enc(const float* __restrict__ obs, int B, int nTiles,
      const float* __restrict__ seW1, const float* __restrict__ seb1,
      const float* __restrict__ seg_, const float* __restrict__ seb_,
      const void* pxm, const void* pym, float Ninv) {
    extern __shared__ char sm[];
    float* bs = (float*)(sm + O_BIAS);
    float* fold = (float*)(sm + O_FOLD);
    u32 smb = smem_u32(sm);
    int tid = threadIdx.x, wid = tid >> 5, lane = tid & 31;

    {
        const float4* s1 = (const float4*)g_Wh;
        const float4* s2 = (const float4*)g_Wl;
        float4* d1 = (float4*)(sm + O_WH);
        float4* d2 = (float4*)(sm + O_WL);
        for (int i = tid; i < 2816; i += 512) { d1[i] = s1[i]; d2[i] = s2[i]; }
    }
    if (tid < 256) bs[tid] = g_bias[tid];
    if (blockIdx.x == 0 && tid < 32) g_hp_stats[tid] = 0.0;
    if (tid < 16) {   // encode BN fold (analytic, from 5 moments)
        const double* st = g_enc_stats;
        double mx = st[0] * Ninv, my = st[1] * Ninv;
        double vxx = st[2] * Ninv - mx * mx;
        double vyy = st[3] * Ninv - my * my;
        double cxy = st[4] * Ninv - mx * my;
        float w0 = seW1[2 * tid], w1 = seW1[2 * tid + 1];
        float mu = (float)(w0 * mx + w1 * my) + seb1[tid];
        float var = (float)((double)w0 * w0 * vxx + (double)w1 * w1 * vyy +
                            2.0 * (double)w0 * w1 * cxy);
        float sc = seg_[tid] * rsqrtf(var + EPSBN);
        float ix = 1.f / scalar_f(pxm), iy = 1.f / scalar_f(pym);
        fold[tid]      = w0 * sc * ix;
        fold[16 + tid] = w1 * sc * iy;
        fold[32 + tid] = (seb1[tid] - mu) * sc + seb_[tid];
    }
    __syncthreads();

    int wm = wid & 1, wn = wid >> 1;
    int j0 = wn * 8 + (lane & 3) * 2;
    float bj[4][2];
#pragma unroll
    for (int g = 0; g < 4; g++) { bj[g][0] = bs[g * 64 + j0]; bj[g][1] = bs[g * 64 + j0 + 1]; }

    u32 bh[3][4][2];
    {
        u32 nrow = (u32)(wn * 8 + (lane & 7));
        u32 gsel = (u32)(((lane >> 4) & 1) * 64);
        u32 ksel = (u32)(((lane >> 3) & 1) * 16);
#pragma unroll
        for (int kt = 0; kt < 3; kt++) {
#pragma unroll
            for (int p = 0; p < 2; p++) {
                u32 r4[4];
                ldsm4(r4, smb + O_WH +
                      ((u32)(p * 2) * 64 + gsel + nrow) * (WSTR * 2) + ksel + (u32)(kt * 32));
                bh[kt][2 * p][0] = r4[0]; bh[kt][2 * p][1] = r4[1];
                bh[kt][2 * p + 1][0] = r4[2]; bh[kt][2 * p + 1][1] = r4[3];
            }
        }
    }

    u32 aRowOff = (u32)((wm * 32 + (lane & 15)) * (WSTR * 2));
    u32 aColSel = (u32)(((lane >> 4) & 1) * 16);
    u32 bRow = (u32)(wn * 8 + (lane & 7));
    u32 bGsel = (u32)(((lane >> 4) & 1) * 64);
    u32 bKsel = (u32)(((lane >> 3) & 1) * 16);
    int srow = tid >> 3, seg8 = tid & 7, j2 = seg8 * 2;
    float fa0 = fold[j2], fb0 = fold[16 + j2], fc0 = fold[32 + j2];
    float fa1 = fold[j2 + 1], fb1 = fold[16 + j2 + 1], fc1 = fold[32 + j2 + 1];

    // prologue: stage feats t0 of first tile into buf0
    {
        int r = blockIdx.x * 64 + srow;
        float2 xy0 = *(const float2*)(obs + 2 * (size_t)r);
        float f0 = fmaxf(fa0 * xy0.x + fb0 * xy0.y + fc0, 0.f);
        float f1 = fmaxf(fa1 * xy0.x + fb1 * xy0.y + fc1, 0.f);
        int off = srow * (WSTR * 2) + j2 * 2;
        *(u32*)(sm + O_AB0 + off) = pack_bf16_hi(f0, f1);
        *(u32*)(sm + O_AB0 + 11264 + off) = pack_bf16_lo(f0, f1);
    }

    for (int tile = blockIdx.x; tile < nTiles; tile += gridDim.x) {
        int row0 = tile * 64;
        int nxt = tile + gridDim.x;
        float creg[2][2][2];

        for (int t = 0; t < T_OBS; t++) {
            u32 ahb = smb + O_AB0 + (u32)((t & 1) * 22528);
            u32 alb = ahb + 11264;
            // prefetch next obs (t+1 same tile, or t0 of next tile)
            float2 nxy = make_float2(0.f, 0.f);
            if (t < T_OBS - 1) {
                nxy = *(const float2*)(obs + (size_t)(t + 1) * B * 2 + 2 * (size_t)(row0 + srow));
            } else if (nxt < nTiles) {
                nxy = *(const float2*)(obs + 2 * (size_t)(nxt * 64 + srow));
            }
            __syncthreads();

            float acc[2][4][4];
#pragma unroll
            for (int mt = 0; mt < 2; mt++)
#pragma unroll
                for (int g = 0; g < 4; g++)
#pragma unroll
                    for (int e = 0; e < 4; e++) acc[mt][g][e] = 0.f;
            int nkt = t ? 5 : 1;
#pragma unroll
            for (int kt = 0; kt < 5; kt++) {
                if (kt >= nkt) break;
                u32 kOff = (u32)(kt * 32);
                u32 ah0[4], ah1[4], al0[4], al1[4];
                u32 aAddr = ahb + aRowOff + aColSel + kOff;
                ldsm4(ah0, aAddr);
                ldsm4(ah1, aAddr + 16 * (WSTR * 2));
                u32 aAddrL = alb + aRowOff + aColSel + kOff;
                ldsm4(al0, aAddrL);
                ldsm4(al1, aAddrL + 16 * (WSTR * 2));
                u32 bl[4][2];
#pragma unroll
                for (int p = 0; p < 2; p++) {
                    u32 r4[4];
                    ldsm4(r4, smb + O_WL +
                          ((u32)(p * 2) * 64 + bGsel + bRow) * (WSTR * 2) + bKsel + kOff);
                    bl[2 * p][0] = r4[0]; bl[2 * p][1] = r4[1];
                    bl[2 * p + 1][0] = r4[2]; bl[2 * p + 1][1] = r4[3];
                }
                if (kt < 3) {
#pragma unroll
                    for (int g = 0; g < 4; g++) {
                        mma16816(acc[0][g], ah0, bh[kt][g]);
                        mma16816(acc[1][g], ah1, bh[kt][g]);
                        mma16816(acc[0][g], al0, bh[kt][g]);
                        mma16816(acc[1][g], al1, bh[kt][g]);
                        mma16816(acc[0][g], ah0, bl[g]);
                        mma16816(acc[1][g], ah1, bl[g]);
                    }
                } else {
                    u32 bhd[4][2];
#pragma unroll
                    for (int p = 0; p < 2; p++) {
                        u32 r4[4];
                        ldsm4(r4, smb + O_WH +
                              ((u32)(p * 2) * 64 + bGsel + bRow) * (WSTR * 2) + bKsel + kOff);
                        bhd[2 * p][0] = r4[0]; bhd[2 * p][1] = r4[1];
                        bhd[2 * p + 1][0] = r4[2]; bhd[2 * p + 1][1] = r4[3];
                    }
#pragma unroll
                    for (int g = 0; g < 4; g++) {
                        mma16816(acc[0][g], ah0, bhd[g]);
                        mma16816(acc[1][g], ah1, bhd[g]);
                        mma16816(acc[0][g], al0, bhd[g]);
                        mma16816(acc[1][g], al1, bhd[g]);
                        mma16816(acc[0][g], ah0, bl[g]);
                        mma16816(acc[1][g], ah1, bl[g]);
                    }
                }
            }

            float hn[2][2][2];
#pragma unroll
            for (int mt = 0; mt < 2; mt++)
#pragma unroll
                for (int rr = 0; rr < 2; rr++)
#pragma unroll
                    for (int cc = 0; cc < 2; cc++) {
                        int e = rr * 2 + cc;
                        float iv = acc[mt][0][e] + bj[0][cc];
                        float fv = acc[mt][1][e] + bj[1][cc];
                        float gv = acc[mt][2][e] + bj[2][cc];
                        float ov = acc[mt][3][e] + bj[3][cc];
                        float cold = t ? creg[mt][rr][cc] : 0.f;
                        lstm_cell(iv, fv, gv, ov, cold, creg[mt][rr][cc], hn[mt][rr][cc]);
                    }

            if (t < T_OBS - 1) {
                // write h + feats(t+1) into the OTHER buffer (safe: its readers
                // finished before the sync at the top of this step)
                u32 ahn = smb + O_AB0 + (u32)(((t + 1) & 1) * 22528);
                u32 aln = ahn + 11264;
#pragma unroll
                for (int mt = 0; mt < 2; mt++)
#pragma unroll
                    for (int rr = 0; rr < 2; rr++) {
                        int lrow = wm * 32 + mt * 16 + rr * 8 + (lane >> 2);
                        int off = lrow * (WSTR * 2) + (16 + j0) * 2;
                        *(u32*)(ahn - smb + sm + off) = pack_bf16_hi(hn[mt][rr][0], hn[mt][rr][1]);
                        *(u32*)(aln - smb + sm + off) = pack_bf16_lo(hn[mt][rr][0], hn[mt][rr][1]);
                    }
                float f0 = fmaxf(fa0 * nxy.x + fb0 * nxy.y + fc0, 0.f);
                float f1 = fmaxf(fa1 * nxy.x + fb1 * nxy.y + fc1, 0.f);
                int off = srow * (WSTR * 2) + j2 * 2;
                *(u32*)(ahn - smb + sm + off) = pack_bf16_hi(f0, f1);
                *(u32*)(aln - smb + sm + off) = pack_bf16_lo(f0, f1);
            } else {
#pragma unroll
                for (int mt = 0; mt < 2; mt++)
#pragma unroll
                    for (int rr = 0; rr < 2; rr++) {
                        int r = row0 + wm * 32 + mt * 16 + rr * 8 + (lane >> 2);
                        *(float2*)(g_h + (size_t)r * 64 + j0) =
                            make_float2(hn[mt][rr][0], hn[mt][rr][1]);
                        *(float2*)(g_c + (size_t)r * 64 + j0) =
                            make_float2(creg[mt][rr][0], creg[mt][rr][1]);
                    }
                if (nxt < nTiles) {   // stage t0 feats of next tile into buf0
                    float f0 = fmaxf(fa0 * nxy.x + fb0 * nxy.y + fc0, 0.f);
                    float f1 = fmaxf(fa1 * nxy.x + fb1 * nxy.y + fc1, 0.f);
                    int off = srow * (WSTR * 2) + j2 * 2;
                    *(u32*)(sm + O_AB0 + off) = pack_bf16_hi(f0, f1);
                    *(u32*)(sm + O_AB0 + 11264 + off) = pack_bf16_lo(f0, f1);
                }
            }
        }
    }
}

// ======================= decode LSTM step (double-buffered A) ================
__global__ void __launch_bounds__(512, 1)
k_dec(int B, int nTiles,
      const float* __restrict__ seW1, const float* __restrict__ seb1,
      const float* __restrict__ seg_, const float* __restrict__ seb_, float Ninv) {
    extern __shared__ char sm[];
    float* bs = (float*)(sm + O_BIAS);
    float* fold = (float*)(sm + O_FOLD);
    u32 smb = smem_u32(sm);
    int tid = threadIdx.x, wid = tid >> 5, lane = tid & 31;

    {
        const float4* s1 = (const float4*)g_Wh;
        const float4* s2 = (const float4*)g_Wl;
        float4* d1 = (float4*)(sm + O_WH);
        float4* d2 = (float4*)(sm + O_WL);
        for (int i = tid; i < 2816; i += 512) { d1[i] = s1[i]; d2[i] = s2[i]; }
    }
    if (tid < 256) bs[tid] = g_bias[tid];
    if (blockIdx.x == 0 && tid < 32) g_hp_stats[tid] = 0.0;
    if (tid < 16) {   // decode BN fold from se stats (inputs already in [0,1])
        const double* st = g_se_stats;
        double mx = st[0] * Ninv, my = st[1] * Ninv;
        double vxx = st[2] * Ninv - mx * mx;
        double vyy = st[3] * Ninv - my * my;
        double cxy = st[4] * Ninv - mx * my;
        float w0 = seW1[2 * tid], w1 = seW1[2 * tid + 1];
        float mu = (float)(w0 * mx + w1 * my) + seb1[tid];
        float var = (float)((double)w0 * w0 * vxx + (double)w1 * w1 * vyy +
                            2.0 * (double)w0 * w1 * cxy);
        float sc = seg_[tid] * rsqrtf(var + EPSBN);
        fold[tid]      = w0 * sc;
        fold[16 + tid] = w1 * sc;
        fold[32 + tid] = (seb1[tid] - mu) * sc + seb_[tid];
    }
    __syncthreads();

    int wm = wid & 1, wn = wid >> 1;
    int j0 = wn * 8 + (lane & 3) * 2;
    float bj[4][2];
#pragma unroll
    for (int g = 0; g < 4; g++) { bj[g][0] = bs[g * 64 + j0]; bj[g][1] = bs[g * 64 + j0 + 1]; }

    u32 bh[3][4][2];
    {
        u32 nrow = (u32)(wn * 8 + (lane & 7));
        u32 gsel = (u32)(((lane >> 4) & 1) * 64);
        u32 ksel = (u32)(((lane >> 3) & 1) * 16);
#pragma unroll
        for (int kt = 0; kt < 3; kt++) {
#pragma unroll
            for (int p = 0; p < 2; p++) {
                u32 r4[4];
                ldsm4(r4, smb + O_WH +
                      ((u32)(p * 2) * 64 + gsel + nrow) * (WSTR * 2) + ksel + (u32)(kt * 32));
                bh[kt][2 * p][0] = r4[0]; bh[kt][2 * p][1] = r4[1];
                bh[kt][2 * p + 1][0] = r4[2]; bh[kt][2 * p + 1][1] = r4[3];
            }
        }
    }

    u32 aRowOff = (u32)((wm * 32 + (lane & 15)) * (WSTR * 2));
    u32 aColSel = (u32)(((lane >> 4) & 1) * 16);
    u32 bRow = (u32)(wn * 8 + (lane & 7));
    u32 bGsel = (u32)(((lane >> 4) & 1) * 64);
    u32 bKsel = (u32)(((lane >> 3) & 1) * 16);
    int srow = tid >> 3, seg8 = tid & 7, j2 = seg8 * 2;
    float fa0 = fold[j2], fb0 = fold[16 + j2], fc0 = fold[32 + j2];
    float fa1 = fold[j2 + 1], fb1 = fold[16 + j2 + 1], fc1 = fold[32 + j2 + 1];

    // prologue: stage first tile into buf0
    {
        int r = blockIdx.x * 64 + srow;
        const float4* hp = (const float4*)(g_h + (size_t)r * 64 + seg8 * 8);
        float4 h0 = hp[0], h1 = hp[1];
        float2 lp = *(const float2*)(g_last + 2 * (size_t)r);
        uint4 hi, lo;
        hi.x = pack_bf16_hi(h0.x, h0.y); lo.x = pack_bf16_lo(h0.x, h0.y);
        hi.y = pack_bf16_hi(h0.z, h0.w); lo.y = pack_bf16_lo(h0.z, h0.w);
        hi.z = pack_bf16_hi(h1.x, h1.y); lo.z = pack_bf16_lo(h1.x, h1.y);
        hi.w = pack_bf16_hi(h1.z, h1.w); lo.w = pack_bf16_lo(h1.z, h1.w);
        int off = srow * (WSTR * 2) + 32 + seg8 * 16;
        *(uint4*)(sm + O_AB0 + off) = hi;
        *(uint4*)(sm + O_AB0 + 11264 + off) = lo;
        float f0 = fmaxf(fa0 * lp.x + fb0 * lp.y + fc0, 0.f);
        float f1 = fmaxf(fa1 * lp.x + fb1 * lp.y + fc1, 0.f);
        int offf = srow * (WSTR * 2) + j2 * 2;
        *(u32*)(sm + O_AB0 + offf) = pack_bf16_hi(f0, f1);
        *(u32*)(sm + O_AB0 + 11264 + offf) = pack_bf16_lo(f0, f1);
    }

    int pbuf = 0;
    for (int tile = blockIdx.x; tile < nTiles; tile += gridDim.x) {
        int row0 = tile * 64;
        int nxt = tile + gridDim.x;
        u32 ahb = smb + O_AB0 + (u32)(pbuf * 22528);
        u32 alb = ahb + 11264;

        // prefetch next tile's inputs (hide LDG behind MMA)
        float4 nh0, nh1; float2 nlp;
        bool hasNext = (nxt < nTiles);
        if (hasNext) {
            int r = nxt * 64 + srow;
            const float4* hp = (const float4*)(g_h + (size_t)r * 64 + seg8 * 8);
            nh0 = hp[0]; nh1 = hp[1];
            nlp = *(const float2*)(g_last + 2 * (size_t)r);
        }
        __syncthreads();

        float acc[2][4][4];
#pragma unroll
        for (int mt = 0; mt < 2; mt++)
#pragma unroll
            for (int g = 0; g < 4; g++)
#pragma unroll
                for (int e = 0; e < 4; e++) acc[mt][g][e] = 0.f;

#pragma unroll
        for (int kt = 0; kt < 5; kt++) {
            u32 kOff = (u32)(kt * 32);
            u32 ah0[4], ah1[4], al0[4], al1[4];
            u32 aAddr = ahb + aRowOff + aColSel + kOff;
            ldsm4(ah0, aAddr);
            ldsm4(ah1, aAddr + 16 * (WSTR * 2));
            u32 aAddrL = alb + aRowOff + aColSel + kOff;
            ldsm4(al0, aAddrL);
            ldsm4(al1, aAddrL + 16 * (WSTR * 2));
            u32 bl[4][2];
#pragma unroll
            for (int p = 0; p < 2; p++) {
                u32 r4[4];
                ldsm4(r4, smb + O_WL +
                      ((u32)(p * 2) * 64 + bGsel + bRow) * (WSTR * 2) + bKsel + kOff);
                bl[2 * p][0] = r4[0]; bl[2 * p][1] = r4[1];
                bl[2 * p + 1][0] = r4[2]; bl[2 * p + 1][1] = r4[3];
            }
            if (kt < 3) {
#pragma unroll
                for (int g = 0; g < 4; g++) {
                    mma16816(acc[0][g], ah0, bh[kt][g]);
                    mma16816(acc[1][g], ah1, bh[kt][g]);
                    mma16816(acc[0][g], al0, bh[kt][g]);
                    mma16816(acc[1][g], al1, bh[kt][g]);
                    mma16816(acc[0][g], ah0, bl[g]);
                    mma16816(acc[1][g], ah1, bl[g]);
                }
            } else {
                u32 bhd[4][2];
#pragma unroll
                for (int p = 0; p < 2; p++) {
                    u32 r4[4];
                    ldsm4(r4, smb + O_WH +
                          ((u32)(p * 2) * 64 + bGsel + bRow) * (WSTR * 2) + bKsel + kOff);
                    bhd[2 * p][0] = r4[0]; bhd[2 * p][1] = r4[1];
                    bhd[2 * p + 1][0] = r4[2]; bhd[2 * p + 1][1] = r4[3];
                }
#pragma unroll
                for (int g = 0; g < 4; g++) {
                    mma16816(acc[0][g], ah0, bhd[g]);
                    mma16816(acc[1][g], ah1, bhd[g]);
                    mma16816(acc[0][g], al0, bhd[g]);
                    mma16816(acc[1][g], al1, bhd[g]);
                    mma16816(acc[0][g], ah0, bl[g]);
                    mma16816(acc[1][g], ah1, bl[g]);
                }
            }
        }

        // epilogue: pointwise -> global h, c
#pragma unroll
        for (int mt = 0; mt < 2; mt++)
#pragma unroll
            for (int rr = 0; rr < 2; rr++) {
                int rw = row0 + wm * 32 + mt * 16 + rr * 8 + (lane >> 2);
                float2 c2 = *(float2*)(g_c + (size_t)rw * 64 + j0);
                float cn[2], hn[2];
#pragma unroll
                for (int cc = 0; cc < 2; cc++) {
                    int e = rr * 2 + cc;
                    float iv = acc[mt][0][e] + bj[0][cc];
                    float fv = acc[mt][1][e] + bj[1][cc];
                    float gv = acc[mt][2][e] + bj[2][cc];
                    float ov = acc[mt][3][e] + bj[3][cc];
                    lstm_cell(iv, fv, gv, ov, cc ? c2.y : c2.x, cn[cc], hn[cc]);
                }
                *(float2*)(g_c + (size_t)rw * 64 + j0) = make_float2(cn[0], cn[1]);
                *(float2*)(g_h + (size_t)rw * 64 + j0) = make_float2(hn[0], hn[1]);
            }

        // stage next tile into the other buffer (readers of it finished
        // before the sync at the top of this iteration)
        if (hasNext) {
            u32 off1 = (u32)(O_AB0 + (pbuf ^ 1) * 22528);
            uint4 hi, lo;
            hi.x = pack_bf16_hi(nh0.x, nh0.y); lo.x = pack_bf16_lo(nh0.x, nh0.y);
            hi.y = pack_bf16_hi(nh0.z, nh0.w); lo.y = pack_bf16_lo(nh0.z, nh0.w);
            hi.z = pack_bf16_hi(nh1.x, nh1.y); lo.z = pack_bf16_lo(nh1.x, nh1.y);
            hi.w = pack_bf16_hi(nh1.z, nh1.w); lo.w = pack_bf16_lo(nh1.z, nh1.w);
            int off = srow * (WSTR * 2) + 32 + seg8 * 16;
            *(uint4*)(sm + off1 + off) = hi;
            *(uint4*)(sm + off1 + 11264 + off) = lo;
            float f0 = fmaxf(fa0 * nlp.x + fb0 * nlp.y + fc0, 0.f);
            float f1 = fmaxf(fa1 * nlp.x + fb1 * nlp.y + fc1, 0.f);
            int offf = srow * (WSTR * 2) + j2 * 2;
            *(u32*)(sm + off1 + offf) = pack_bf16_hi(f0, f1);
            *(u32*)(sm + off1 + 11264 + offf) = pack_bf16_lo(f0, f1);
        }
        pbuf ^= 1;
    }
}

// ---------------- hidden2pos proj + stats (1 row/thread) --------------------
__global__ void k_hp(const float* __restrict__ hpW1, const float* __restrict__ hpb1, int B) {
    __shared__ float Ws[1024];
    __shared__ float red[8][32];
    for (int i = threadIdx.x; i < 1024; i += 256) Ws[i] = hpW1[i];
    if (blockIdx.x == 0 && threadIdx.x < 5) g_se_stats[threadIdx.x] = 0.0;
    __syncthreads();
    int r = blockIdx.x * 256 + threadIdx.x;
    float z[16];
#pragma unroll
    for (int jj = 0; jj < 16; jj++) z[jj] = __ldg(hpb1 + jj);
    const float4* ha = (const float4*)(g_h + (size_t)r * 64);
#pragma unroll
    for (int kk = 0; kk < 16; kk++) {
        float4 a = ha[kk];
#pragma unroll
        for (int jj = 0; jj < 16; jj++) {
            const float* w = &Ws[jj * 64 + 4 * kk];
            z[jj] += a.x * w[0] + a.y * w[1] + a.z * w[2] + a.w * w[3];
        }
    }
    float4* zo = (float4*)(g_z + (size_t)r * 16);
    zo[0] = make_float4(z[0], z[1], z[2], z[3]);
    zo[1] = make_float4(z[4], z[5], z[6], z[7]);
    zo[2] = make_float4(z[8], z[9], z[10], z[11]);
    zo[3] = make_float4(z[12], z[13], z[14], z[15]);
    float sv[16], qv[16];
#pragma unroll
    for (int jj = 0; jj < 16; jj++) { sv[jj] = z[jj]; qv[jj] = z[jj] * z[jj]; }
    int wid = threadIdx.x >> 5, lane = threadIdx.x & 31;
#pragma unroll
    for (int jj = 0; jj < 16; jj++) { sv[jj] = wred(sv[jj]); qv[jj] = wred(qv[jj]); }
    if (lane == 0) {
#pragma unroll
        for (int jj = 0; jj < 16; jj++) { red[wid][jj] = sv[jj]; red[wid][16 + jj] = qv[jj]; }
    }
    __syncthreads();
    if (wid == 0) {
        float t = 0.f;
#pragma unroll
        for (int w = 0; w < 8; w++) t += red[w][lane];
        atomicAdd(&g_hp_stats[lane], (double)t);
    }
}

// ---------------- positions: BN(inline)+relu+W2, sigmoid, out, se moments ---
__global__ void k_pos(const float* __restrict__ hpW2, const float* __restrict__ hpb2,
                      const float* __restrict__ gamma, const float* __restrict__ beta,
                      float* __restrict__ out, const void* pxm, const void* pym,
                      float Binv, int B) {
    __shared__ float sc[16], sh[16];
    __shared__ float red[8][5];
    if (threadIdx.x < 16) {
        int j = threadIdx.x;
        double mu = g_hp_stats[j] * Binv;
        double var = g_hp_stats[16 + j] * Binv - mu * mu;
        float s = gamma[j] * rsqrtf((float)var + EPSBN);
        sc[j] = s;
        sh[j] = beta[j] - (float)mu * s;
    }
    __syncthreads();
    int row = blockIdx.x * 256 + threadIdx.x;
    const float4* zr = (const float4*)(g_z + (size_t)row * 16);
    float px = hpb2[0], py = hpb2[1];
#pragma unroll
    for (int q4 = 0; q4 < 4; q4++) {
        float4 v = zr[q4];
        float vv[4] = {v.x, v.y, v.z, v.w};
#pragma unroll
        for (int e = 0; e < 4; e++) {
            int j = q4 * 4 + e;
            float t = fmaxf(vv[e] * sc[j] + sh[j], 0.f);
            px += t * hpW2[j];
            py += t * hpW2[16 + j];
        }
    }
    float lx = fast_sig(px + g_last[2 * row]);
    float ly = fast_sig(py + g_last[2 * row + 1]);
    g_last[2 * row] = lx;
    g_last[2 * row + 1] = ly;
    out[2 * row]     = lx * scalar_f(pxm);
    out[2 * row + 1] = ly * scalar_f(pym);
    float s[5] = {lx, ly, lx * lx, ly * ly, lx * ly};
    int wid = threadIdx.x >> 5, lane = threadIdx.x & 31;
#pragma unroll
    for (int k = 0; k < 5; k++) s[k] = wred(s[k]);
    if (lane == 0) {
#pragma unroll
        for (int k = 0; k < 5; k++) red[wid][k] = s[k];
    }
    __syncthreads();
    if (wid == 0 && lane < 5) {
        float t = 0.f;
#pragma unroll
        for (int w = 0; w < 8; w++) t += red[w][lane];
        atomicAdd(&g_se_stats[lane], (double)t);
    }
}

// ---------------- launch ------------------------------------------------------
extern "C" void kernel_launch(void* const* d_in, const int* in_sizes, int n_in,
                              void* d_out, int out_size) {
    const float* obs  = (const float*)d_in[0];
    const float* seW1 = (const float*)d_in[1];
    const float* seb1 = (const float*)d_in[2];
    const float* seg  = (const float*)d_in[3];
    const float* seb  = (const float*)d_in[4];
    const float* seW2 = (const float*)d_in[5];
    const float* seb2 = (const float*)d_in[6];
    const float* hpW1 = (const float*)d_in[7];
    const float* hpb1 = (const float*)d_in[8];
    const float* hpg  = (const float*)d_in[9];
    const float* hpb  = (const float*)d_in[10];
    const float* hpW2 = (const float*)d_in[11];
    const float* hpb2 = (const float*)d_in[12];
    const float* Wih  = (const float*)d_in[13];
    const float* Whh  = (const float*)d_in[14];
    const float* bih  = (const float*)d_in[15];
    const float* bhh  = (const float*)d_in[16];
    const void*  pxm  = d_in[17];
    const void*  pym  = d_in[18];

    int B = in_sizes[0] / (T_OBS * 2);
    int TB = T_OBS * B;
    int predLen = out_size / (2 * B);
    float* out = (float*)d_out;
    int nTiles = B / 64;

    cudaFuncSetAttribute(k_enc, cudaFuncAttributeMaxDynamicSharedMemorySize, LSTM_SMEM);
    cudaFuncSetAttribute(k_dec, cudaFuncAttributeMaxDynamicSharedMemorySize, LSTM_SMEM);

    k_prep<<<1, 256>>>(Wih, Whh, bih, bhh, seW2, seb2);
    k_moments<<<512, 256>>>(obs, pxm, pym, TB, B);
    k_enc<<<148, 512, LSTM_SMEM>>>(obs, B, nTiles, seW1, seb1, seg, seb,
                                   pxm, pym, 1.0f / (float)TB);

    for (int s = 0; s < predLen; s++) {
        k_hp<<<B / 256, 256>>>(hpW1, hpb1, B);
        k_pos<<<B / 256, 256>>>(hpW2, hpb2, hpg, hpb, out + (size_t)s * B * 2,
                                pxm, pym, 1.0f / (float)B, B);
        if (s + 1 < predLen)
            k_dec<<<148, 512, LSTM_SMEM>>>(B, nTiles, seW1, seb1, seg, seb,
                                           1.0f / (float)B);
    }
}